// round 9
// baseline (speedup 1.0000x reference)
#include <cuda_runtime.h>
#include <cuda_fp16.h>
#include <math.h>
#include <stdint.h>

#define HID    1024
#define NHEADS 16
#define HDIM   64
#define SEQ    2048
#define BATCH  2
#define TOKS   (BATCH*SEQ)   // 4096
#define NELEM  (BATCH*NHEADS*SEQ*HDIM)

// fp16 scratch
__device__ __align__(16) __half g_Qf[NELEM], g_Kf[NELEM], g_Vf[NELEM]; // [B,NH,S,HD]
__device__ __align__(16) __half g_Ah[TOKS*HID], g_Al[TOKS*HID];        // hidden hi/lo
__device__ __align__(16) __half g_Wf[3*HID*HID];                       // Wq,Wk,Wv fp16

// ===================== helpers =====================
__device__ __forceinline__ uint32_t smem_u32(const void* p) {
    uint32_t a;
    asm("{ .reg .u64 t; cvta.to.shared.u64 t, %1; cvt.u32.u64 %0, t; }"
        : "=r"(a) : "l"(p));
    return a;
}
__device__ __forceinline__ void ldsm4(uint32_t* r, uint32_t a) {
    asm volatile("ldmatrix.sync.aligned.m8n8.x4.shared.b16 {%0,%1,%2,%3}, [%4];"
        : "=r"(r[0]), "=r"(r[1]), "=r"(r[2]), "=r"(r[3]) : "r"(a));
}
__device__ __forceinline__ void ldsm4t(uint32_t* r, uint32_t a) {
    asm volatile("ldmatrix.sync.aligned.m8n8.x4.trans.shared.b16 {%0,%1,%2,%3}, [%4];"
        : "=r"(r[0]), "=r"(r[1]), "=r"(r[2]), "=r"(r[3]) : "r"(a));
}
__device__ __forceinline__ void mmaf16(float* d, const uint32_t* a, const uint32_t* b) {
    asm volatile(
        "mma.sync.aligned.m16n8k16.row.col.f32.f16.f16.f32 "
        "{%0,%1,%2,%3}, {%4,%5,%6,%7}, {%8,%9}, {%0,%1,%2,%3};"
        : "+f"(d[0]), "+f"(d[1]), "+f"(d[2]), "+f"(d[3])
        : "r"(a[0]), "r"(a[1]), "r"(a[2]), "r"(a[3]), "r"(b[0]), "r"(b[1]));
}
__device__ __forceinline__ uint32_t pack_h(float x, float y) {
    __half2 h = __floats2half2_rn(x, y);
    return *reinterpret_cast<uint32_t*>(&h);
}
__device__ __forceinline__ uint32_t pack_hlo(float x, float y, uint32_t hi) {
    __half2 h = *reinterpret_cast<__half2*>(&hi);
    return pack_h(x - __half2float(h.x), y - __half2float(h.y));
}
__device__ __forceinline__ void cpa16(uint32_t s, const void* g) {
    asm volatile("{\n\t.reg .u64 gp;\n\tcvta.to.global.u64 gp, %1;\n\t"
                 "cp.async.cg.shared.global [%0], [gp], 16;\n\t}"
                 :: "r"(s), "l"(g) : "memory");
}
#define CP_COMMIT() asm volatile("cp.async.commit_group;" ::: "memory")
#define CP_WAIT1()  asm volatile("cp.async.wait_group 1;" ::: "memory")
#define CP_WAIT0()  asm volatile("cp.async.wait_group 0;" ::: "memory")

// ===========================================================================
// Kernel 0: one-shot fp32 -> fp16 conversion (hidden hi/lo, W single).
// ===========================================================================
#define H4  (TOKS*HID/4)    // 1048576 float4 slots (hidden)
#define W4  (HID*HID/4)     // 262144 per weight matrix

__global__ __launch_bounds__(256)
void conv_pre(const float4* __restrict__ hidden, const float4* __restrict__ Wq,
              const float4* __restrict__ Wk, const float4* __restrict__ Wv)
{
    int idx = blockIdx.x * blockDim.x + threadIdx.x;
    if (idx < H4) {
        float4 a = hidden[idx];
        uint32_t h0 = pack_h(a.x, a.y), h1 = pack_h(a.z, a.w);
        ((uint2*)g_Ah)[idx] = make_uint2(h0, h1);
        ((uint2*)g_Al)[idx] =
            make_uint2(pack_hlo(a.x, a.y, h0), pack_hlo(a.z, a.w, h1));
    } else {
        int w = idx - H4;
        int which = w / W4;
        int off   = w - which * W4;
        const float4* W = (which == 0) ? Wq : ((which == 1) ? Wk : Wv);
        float4 v = W[off];
        ((uint2*)g_Wf)[(size_t)which * W4 + off] =
            make_uint2(pack_h(v.x, v.y), pack_h(v.z, v.w));
    }
}

// ===========================================================================
// Kernel 1: QKV projection, fp16 2-MMA (A hi/lo, W single), cp.async
// double-buffered from pre-converted fp16 gmem. CTA 128x128, BK=32, 2 CTAs/SM.
// ===========================================================================
#define AP 40
#define QARR   (128*AP*2)      // 10240 B per array
#define QSTAGE (3*QARR)        // Ah, Al, W
#define QKV_SMEM (2*QSTAGE)    // 61440

__global__ __launch_bounds__(256, 2)
void qkv_mma(const float* __restrict__ bq, const float* __restrict__ bk,
             const float* __restrict__ bv)
{
    extern __shared__ char qsm[];
    const uint32_t sb = smem_u32(qsm);

    const int z = blockIdx.z;
    const float* bias = (z == 0) ? bq : ((z == 1) ? bk : bv);
    __half* dst       = (z == 0) ? g_Qf : ((z == 1) ? g_Kf : g_Vf);
    const __half* Wz  = g_Wf + (size_t)z * HID * HID;
    const float oscale = (z == 0) ? 0.125f * 1.4426950408889634f : 1.0f;

    const int tid  = threadIdx.x;
    const int lane = tid & 31;
    const int wid  = tid >> 5;
    const int wm   = wid >> 2;
    const int wn   = wid & 3;
    const int m0   = blockIdx.y * 128;
    const int n0   = blockIdx.x * 128;

    // loader mapping: 512 chunks per array, 2 per thread
    const int r0row = tid >> 2, r0c = (tid & 3) * 8;            // chunks 0..255
    const int r1row = (tid + 256) >> 2, r1c = ((tid + 256) & 3) * 8;

    auto issue = [&](uint32_t stg, int kt) {
        cpa16(stg + 0*QARR + (uint32_t)((r0row * AP + r0c) * 2),
              g_Ah + (size_t)(m0 + r0row) * HID + kt + r0c);
        cpa16(stg + 0*QARR + (uint32_t)((r1row * AP + r1c) * 2),
              g_Ah + (size_t)(m0 + r1row) * HID + kt + r1c);
        cpa16(stg + 1*QARR + (uint32_t)((r0row * AP + r0c) * 2),
              g_Al + (size_t)(m0 + r0row) * HID + kt + r0c);
        cpa16(stg + 1*QARR + (uint32_t)((r1row * AP + r1c) * 2),
              g_Al + (size_t)(m0 + r1row) * HID + kt + r1c);
        cpa16(stg + 2*QARR + (uint32_t)((r0row * AP + r0c) * 2),
              Wz + (size_t)(n0 + r0row) * HID + kt + r0c);
        cpa16(stg + 2*QARR + (uint32_t)((r1row * AP + r1c) * 2),
              Wz + (size_t)(n0 + r1row) * HID + kt + r1c);
        CP_COMMIT();
    };

    float acc[4][4][4];
    #pragma unroll
    for (int mt = 0; mt < 4; mt++)
        #pragma unroll
        for (int nt = 0; nt < 4; nt++)
            #pragma unroll
            for (int q = 0; q < 4; q++) acc[mt][nt][q] = 0.0f;

    issue(sb, 0);

    const int NIT = HID / 32;   // 32
    for (int it = 0; it < NIT; it++) {
        if (it + 1 < NIT) { issue(sb + ((it + 1) & 1) * QSTAGE, (it + 1) * 32); CP_WAIT1(); }
        else              { CP_WAIT0(); }
        __syncthreads();

        const uint32_t stg = sb + (it & 1) * QSTAGE;
        const uint32_t aAh = stg, aAl = stg + QARR, aB = stg + 2*QARR;

        #pragma unroll
        for (int ks = 0; ks < 2; ks++) {
            uint32_t ah[4][4], al[4][4], bf[4][2];
            const int arow = wm * 64 + (lane & 15);
            const int acol = ks * 16 + ((lane >> 4) << 3);
            #pragma unroll
            for (int mt = 0; mt < 4; mt++) {
                uint32_t off = (uint32_t)(((arow + mt * 16) * AP + acol) * 2);
                ldsm4(ah[mt], aAh + off);
                ldsm4(al[mt], aAl + off);
            }
            const int brow = wn * 32 + (lane & 7) + ((lane >> 4) << 3);
            const int bcol = ks * 16 + ((lane >> 3) & 1) * 8;
            #pragma unroll
            for (int np = 0; np < 2; np++) {
                uint32_t off = (uint32_t)(((brow + np * 16) * AP + bcol) * 2);
                uint32_t r4[4];
                ldsm4(r4, aB + off);
                bf[np*2][0] = r4[0]; bf[np*2][1] = r4[1];
                bf[np*2+1][0] = r4[2]; bf[np*2+1][1] = r4[3];
            }
            #pragma unroll
            for (int mt = 0; mt < 4; mt++)
                #pragma unroll
                for (int nt = 0; nt < 4; nt++) {
                    mmaf16(acc[mt][nt], ah[mt], bf[nt]);
                    mmaf16(acc[mt][nt], al[mt], bf[nt]);
                }
        }
        __syncthreads();
    }

    // epilogue: add bias, scale (Q), round to fp16, scatter to [B,NH,S,HD]
    #pragma unroll
    for (int mt = 0; mt < 4; mt++) {
        int r = m0 + wm * 64 + mt * 16 + (lane >> 2);
        int b = r >> 11;
        int s = r & (SEQ - 1);
        #pragma unroll
        for (int nt = 0; nt < 4; nt++) {
            int o = n0 + wn * 32 + nt * 8 + 2 * (lane & 3);
            int h = o >> 6;
            int d = o & (HDIM - 1);
            size_t p = (((size_t)b * NHEADS + h) * SEQ + s) * HDIM + d;
            float x0 = (acc[mt][nt][0] + bias[o])     * oscale;
            float x1 = (acc[mt][nt][1] + bias[o + 1]) * oscale;
            float x2 = (acc[mt][nt][2] + bias[o])     * oscale;
            float x3 = (acc[mt][nt][3] + bias[o + 1]) * oscale;
            *(uint32_t*)&dst[p] = pack_h(x0, x1);
            *(uint32_t*)&dst[p + 8 * HDIM] = pack_h(x2, x3);
        }
    }
}

// ===========================================================================
// Kernel 2: flash attention fp16 (unchanged from R8).
// ===========================================================================
#define KP 72
#define ARRB  (64*KP*2)
#define STAGEB (2*ARRB)
#define ATTN_SMEM (2*STAGEB)
#define NT (SEQ/64)

__global__ __launch_bounds__(256, 2)
void attn_mma(float* __restrict__ out)
{
    extern __shared__ char smem[];
    const uint32_t sb = smem_u32(smem);

    const int tid  = threadIdx.x;
    const int lane = tid & 31;
    const int wid  = tid >> 5;
    const int q0   = blockIdx.x * 128;
    const int bh   = blockIdx.y;
    const size_t base = (size_t)bh * SEQ * HDIM;

    const int crow = tid >> 3;
    const int cch  = (tid & 7) * 8;

    {
        #pragma unroll
        for (int r = 0; r < 4; r++) {
            const __half* g = (r < 2) ? g_Kf : g_Vf;
            int arr = r >> 1;
            int row = (r & 1) * 32 + crow;
            cpa16(sb + arr * ARRB + (uint32_t)((row * KP + cch) * 2),
                  g + base + (size_t)row * HDIM + cch);
        }
        CP_COMMIT();
    }

    const int qrow = q0 + wid * 16 + (lane >> 2);
    const int qc   = 2 * (lane & 3);
    uint32_t qf[4][4];
    #pragma unroll
    for (int kt = 0; kt < 4; kt++) {
        int c = kt * 16 + qc;
        qf[kt][0] = *(const uint32_t*)&g_Qf[base + (size_t)qrow * HDIM + c];
        qf[kt][1] = *(const uint32_t*)&g_Qf[base + (size_t)(qrow + 8) * HDIM + c];
        qf[kt][2] = *(const uint32_t*)&g_Qf[base + (size_t)qrow * HDIM + c + 8];
        qf[kt][3] = *(const uint32_t*)&g_Qf[base + (size_t)(qrow + 8) * HDIM + c + 8];
    }

    float m[2] = { -INFINITY, -INFINITY };
    float l[2] = { 0.0f, 0.0f };
    float o[8][4];
    #pragma unroll
    for (int nt = 0; nt < 8; nt++)
        #pragma unroll
        for (int q = 0; q < 4; q++) o[nt][q] = 0.0f;

    for (int t = 0; t < NT; t++) {
        if (t + 1 < NT) {
            const uint32_t st1 = ((t + 1) & 1) * STAGEB;
            const size_t goff = base + (size_t)(t + 1) * 64 * HDIM;
            #pragma unroll
            for (int r = 0; r < 4; r++) {
                const __half* g = (r < 2) ? g_Kf : g_Vf;
                int arr = r >> 1;
                int row = (r & 1) * 32 + crow;
                cpa16(sb + st1 + arr * ARRB + (uint32_t)((row * KP + cch) * 2),
                      g + goff + (size_t)row * HDIM + cch);
            }
            CP_COMMIT();
            CP_WAIT1();
        } else {
            CP_WAIT0();
        }
        __syncthreads();

        const uint32_t stg = (t & 1) * STAGEB;
        const uint32_t aK = sb + stg;
        const uint32_t aV = aK + ARRB;

        float s[8][4];
        #pragma unroll
        for (int nt = 0; nt < 8; nt++)
            #pragma unroll
            for (int q = 0; q < 4; q++) s[nt][q] = 0.0f;

        #pragma unroll
        for (int ks = 0; ks < 4; ks++) {
            const int krow = (lane & 7) + ((lane >> 4) << 3);
            const int kcol = ks * 16 + ((lane >> 3) & 1) * 8;
            #pragma unroll
            for (int np = 0; np < 4; np++) {
                uint32_t off = (uint32_t)(((krow + np * 16) * KP + kcol) * 2);
                uint32_t rk[4];
                ldsm4(rk, aK + off);
                uint32_t b0[2] = { rk[0], rk[1] }, b1[2] = { rk[2], rk[3] };
                mmaf16(s[np*2],   qf[ks], b0);
                mmaf16(s[np*2+1], qf[ks], b1);
            }
        }

        float sc0, sc1;
        {
            float mt = -INFINITY;
            #pragma unroll
            for (int nt = 0; nt < 8; nt++)
                mt = fmaxf(mt, fmaxf(s[nt][0], s[nt][1]));
            mt = fmaxf(mt, __shfl_xor_sync(0xffffffffu, mt, 1));
            mt = fmaxf(mt, __shfl_xor_sync(0xffffffffu, mt, 2));
            float mn = fmaxf(m[0], mt);
            sc0 = exp2f(m[0] - mn);
            m[0] = mn;
            float ps = 0.0f;
            #pragma unroll
            for (int nt = 0; nt < 8; nt++) {
                s[nt][0] = exp2f(s[nt][0] - mn);
                s[nt][1] = exp2f(s[nt][1] - mn);
                ps += s[nt][0] + s[nt][1];
            }
            ps += __shfl_xor_sync(0xffffffffu, ps, 1);
            ps += __shfl_xor_sync(0xffffffffu, ps, 2);
            l[0] = l[0] * sc0 + ps;
        }
        {
            float mt = -INFINITY;
            #pragma unroll
            for (int nt = 0; nt < 8; nt++)
                mt = fmaxf(mt, fmaxf(s[nt][2], s[nt][3]));
            mt = fmaxf(mt, __shfl_xor_sync(0xffffffffu, mt, 1));
            mt = fmaxf(mt, __shfl_xor_sync(0xffffffffu, mt, 2));
            float mn = fmaxf(m[1], mt);
            sc1 = exp2f(m[1] - mn);
            m[1] = mn;
            float ps = 0.0f;
            #pragma unroll
            for (int nt = 0; nt < 8; nt++) {
                s[nt][2] = exp2f(s[nt][2] - mn);
                s[nt][3] = exp2f(s[nt][3] - mn);
                ps += s[nt][2] + s[nt][3];
            }
            ps += __shfl_xor_sync(0xffffffffu, ps, 1);
            ps += __shfl_xor_sync(0xffffffffu, ps, 2);
            l[1] = l[1] * sc1 + ps;
        }
        #pragma unroll
        for (int nt = 0; nt < 8; nt++) {
            o[nt][0] *= sc0; o[nt][1] *= sc0;
            o[nt][2] *= sc1; o[nt][3] *= sc1;
        }

        uint32_t ph[4][4];
        #pragma unroll
        for (int kp = 0; kp < 4; kp++) {
            const int t0 = 2 * kp, t1 = 2 * kp + 1;
            ph[kp][0] = pack_h(s[t0][0], s[t0][1]);
            ph[kp][1] = pack_h(s[t0][2], s[t0][3]);
            ph[kp][2] = pack_h(s[t1][0], s[t1][1]);
            ph[kp][3] = pack_h(s[t1][2], s[t1][3]);
        }

        #pragma unroll
        for (int kp = 0; kp < 4; kp++) {
            const int vrow = kp * 16 + (lane & 7) + (((lane >> 3) & 1) << 3);
            #pragma unroll
            for (int np = 0; np < 4; np++) {
                const int vcol = np * 16 + ((lane >> 4) << 3);
                uint32_t off = (uint32_t)((vrow * KP + vcol) * 2);
                uint32_t rv[4];
                ldsm4t(rv, aV + off);
                uint32_t b0[2] = { rv[0], rv[1] }, b1[2] = { rv[2], rv[3] };
                mmaf16(o[np*2],   ph[kp], b0);
                mmaf16(o[np*2+1], ph[kp], b1);
            }
        }
        __syncthreads();
    }

    const int b = bh >> 4;
    const int h = bh & (NHEADS - 1);
    const float inv0 = 1.0f / l[0];
    const float inv1 = 1.0f / l[1];
    const int r = q0 + wid * 16 + (lane >> 2);
    #pragma unroll
    for (int nt = 0; nt < 8; nt++) {
        int d = nt * 8 + 2 * (lane & 3);
        *(float2*)&out[((size_t)b * SEQ + r) * HID + h * HDIM + d] =
            make_float2(o[nt][0] * inv0, o[nt][1] * inv0);
        *(float2*)&out[((size_t)b * SEQ + r + 8) * HID + h * HDIM + d] =
            make_float2(o[nt][2] * inv1, o[nt][3] * inv1);
    }
}

// ---------------------------------------------------------------------------
extern "C" void kernel_launch(void* const* d_in, const int* in_sizes, int n_in,
                              void* d_out, int out_size)
{
    const float* hidden = (const float*)d_in[0];
    const float* Wq = (const float*)d_in[1];
    const float* bq = (const float*)d_in[2];
    const float* Wk = (const float*)d_in[3];
    const float* bk = (const float*)d_in[4];
    const float* Wv = (const float*)d_in[5];
    const float* bv = (const float*)d_in[6];
    float* out = (float*)d_out;

    conv_pre<<<(H4 + 3 * W4) / 256, 256>>>((const float4*)hidden, (const float4*)Wq,
                                           (const float4*)Wk, (const float4*)Wv);

    cudaFuncSetAttribute(qkv_mma, cudaFuncAttributeMaxDynamicSharedMemorySize, QKV_SMEM);
    qkv_mma<<<dim3(HID / 128, TOKS / 128, 3), 256, QKV_SMEM>>>(bq, bk, bv);

    cudaFuncSetAttribute(attn_mma, cudaFuncAttributeMaxDynamicSharedMemorySize, ATTN_SMEM);
    attn_mma<<<dim3(SEQ / 128, BATCH * NHEADS), 256, ATTN_SMEM>>>(out);
}